// round 17
// baseline (speedup 1.0000x reference)
#include <cuda_runtime.h>
#include <cuda_fp16.h>

// ---------------------------------------------------------------------------
// TensorizedEmbedding: out[b] = core0[d0] x core1[d1] x core2[d2] x core3[d3]
// ROW_DIMS=(8,10,20,20), COL_DIMS=(4,4,6,8), RANKS=(1,16,16,16,1)
//
// R16 (PDL) -> 29.7us; ~8us was still precompute+launch overhead.
// R17: SINGLE fused kernel. First 480 "items" (80 FA + 400 FB) are built by
// the first 480 blocks (bid-ordered wave-1 placement + __launch_bounds__
// (256,4) guarantees they are co-resident -> no deadlock), published through
// a device-wide counter barrier; then all 1024 blocks run the fp16 MMA
// datapath (permuted-B STG.128, reg double-buffer, st.global.wt).
// Counters reset by the last-exiting block -> deterministic across replays.
// ---------------------------------------------------------------------------

// Fragment tables (fp16, MMA m16n8k16 register layout).
// g_FA[comb01][lane=32][reg=4][half=2]  (512B per combo, 40KB total)
// g_FB[comb23][ntp=3][lane=32][reg=4][half=2] (1.5KB per combo, 600KB total)
//   Column permutation: fragment n-position p of sub-tile s in pair ntp maps
//   to global col  ntp*16 + (p>>1)*4 + s*2 + (p&1)  (lane-contiguous stores).
static __device__ __half g_FA[80 * 256];
static __device__ __half g_FB[400 * 768];
static __device__ int    g_done = 0;    // precompute items published
static __device__ int    g_exit = 0;    // blocks finished (for reset)

__device__ __forceinline__ void mma_f16(float* c, float4 a,
                                        unsigned b0, unsigned b1) {
    asm volatile(
        "mma.sync.aligned.m16n8k16.row.col.f32.f16.f16.f32 "
        "{%0,%1,%2,%3},{%4,%5,%6,%7},{%8,%9},{%0,%1,%2,%3};"
        : "+f"(c[0]), "+f"(c[1]), "+f"(c[2]), "+f"(c[3])
        : "r"(__float_as_uint(a.x)), "r"(__float_as_uint(a.y)),
          "r"(__float_as_uint(a.z)), "r"(__float_as_uint(a.w)),
          "r"(b0), "r"(b1));
}

// Write-through 128-bit store (paces DRAM writes, keeps L2 clean of dirty
// output lines across graph replays).
__device__ __forceinline__ void stwt128(float* p, float a, float b,
                                        float c, float d) {
    asm volatile("st.global.wt.v4.b32 [%0], {%1, %2, %3, %4};"
                 :: "l"(p), "f"(a), "f"(b), "f"(c), "f"(d) : "memory");
}

#define T_PER_WARP 4
#define WARPS 8
#define N_ITEMS 480

__global__ __launch_bounds__(256, 4)
void te_fused(const int* __restrict__ x,
              const float* __restrict__ core0,
              const float* __restrict__ core1,
              const float* __restrict__ core2,
              const float* __restrict__ core3,
              float* __restrict__ out, int B) {
    __shared__ float s2[1536];
    __shared__ float s3[128];

    int tid  = threadIdx.x;
    int w    = tid >> 5;
    int lane = tid & 31;
    int base = (blockIdx.x * WARPS + w) * T_PER_WARP;

    // ---- table-independent prologue (x loads overlap precompute) ----
    int myx = 0;
    if (base < B && lane < T_PER_WARP && base + lane < B) myx = x[base + lane];

    // ================= PHASE 1: precompute items =================
    int items_done = 0;
    for (int item = blockIdx.x; item < N_ITEMS; item += gridDim.x) {
        if (item < 80) {
            // FA combo: 256 entries, one per thread
            int comb = item;                   // d0*10 + d1
            int d0 = comb / 10, d1 = comb % 10;
            int e   = tid;
            int l   = e >> 3;
            int rr  = (e >> 1) & 3;
            int h   = e & 1;
            int row = (l >> 2) + (rr & 1) * 8;             // a (m-dim)
            int r2  = (l & 3) * 2 + h + (rr >> 1) * 8;     // k-dim
            int m0  = row >> 2, m1 = row & 3;
            float s = 0.f;
#pragma unroll
            for (int r1 = 0; r1 < 16; ++r1) {
                float v0 = core0[(d0 * 4 + m0) * 16 + r1];             // [1,8,4,16]
                float v1 = core1[((r1 * 10 + d1) * 4 + m1) * 16 + r2]; // [16,10,4,16]
                s += v0 * v1;
            }
            g_FA[comb * 256 + e] = __float2half_rn(s);
        } else {
            int comb = item - 80;              // d2*20 + d3
            int d2 = comb / 20, d3 = comb % 20;
            __syncthreads();   // protect smem reuse across items
            for (int e = tid; e < 1536; e += blockDim.x) {
                int r2 = e / 96, rest = e - r2 * 96;
                int m2 = rest >> 4, r3 = rest & 15;
                s2[e] = core2[((r2 * 20 + d2) * 6 + m2) * 16 + r3];
            }
            for (int e = tid; e < 128; e += blockDim.x) {
                int r3 = e >> 3, m3 = e & 7;
                s3[e] = core3[(r3 * 20 + d3) * 8 + m3];
            }
            __syncthreads();
            for (int e = tid; e < 768; e += blockDim.x) {
                int ntp = e >> 8;                  // 0..2 (nt pair)
                int r8  = e & 255;
                int l   = r8 >> 3;
                int rr  = (r8 >> 1) & 3;
                int h   = r8 & 1;
                int sts = rr >> 1;                 // sub-tile within pair
                int brg = rr & 1;                  // b-register (k-halves)
                int k   = (l & 3) * 2 + h + brg * 8;   // r2 (k-dim)
                int p   = l >> 2;                  // fragment n-position
                int n   = ntp * 16 + (p >> 1) * 4 + sts * 2 + (p & 1);
                int m2  = n >> 3, m3 = n & 7;
                float s = 0.f;
#pragma unroll
                for (int r3 = 0; r3 < 16; ++r3)
                    s += s2[(k * 6 + m2) * 16 + r3] * s3[r3 * 8 + m3];
                g_FB[comb * 768 + e] = __float2half_rn(s);
            }
        }
        ++items_done;
    }

    // Publish this block's items.
    if (items_done) {
        __threadfence();
        __syncthreads();
        if (tid == 0) atomicAdd(&g_done, items_done);
    }

    // ================= BARRIER: wait for all 480 items =================
    if (tid == 0) {
        while (atomicAdd(&g_done, 0) < N_ITEMS) __nanosleep(128);
        __threadfence();
    }
    __syncthreads();

    // ================= PHASE 2: token GEMMs =================
    if (base < B) {
        int g  = lane >> 2;     // fragment row group
        int tq = lane & 3;      // thread-in-group

        // Register double-buffer of fragments: slot = token parity.
        float4 A[2], B0[2], B1[2], B2[2];
        {
            int idx  = __shfl_sync(0xffffffffu, myx, 0);
            int d01  = idx / 400;
            int comb = idx - d01 * 400;
            const float4* pA = (const float4*)g_FA + (size_t)d01 * 32 + lane;
            const float4* pB = (const float4*)g_FB + (size_t)comb * 96 + lane;
            A[0]  = __ldg(pA);
            B0[0] = __ldg(pB);
            B1[0] = __ldg(pB + 32);
            B2[0] = __ldg(pB + 64);
        }

#pragma unroll
        for (int i = 0; i < T_PER_WARP; ++i) {
            int t = base + i;
            if (t >= B) break;
            int cur = i & 1;

            if (i + 1 < T_PER_WARP && t + 1 < B) {
                int nxt  = (i + 1) & 1;
                int idx  = __shfl_sync(0xffffffffu, myx, i + 1);
                int d01  = idx / 400;
                int comb = idx - d01 * 400;
                const float4* pA = (const float4*)g_FA + (size_t)d01 * 32 + lane;
                const float4* pB = (const float4*)g_FB + (size_t)comb * 96 + lane;
                A[nxt]  = __ldg(pA);
                B0[nxt] = __ldg(pB);
                B1[nxt] = __ldg(pB + 32);
                B2[nxt] = __ldg(pB + 64);
            }

            float acc[6][4];
#pragma unroll
            for (int nt = 0; nt < 6; ++nt)
#pragma unroll
                for (int j = 0; j < 4; ++j) acc[nt][j] = 0.f;

            float4 af = A[cur];
            mma_f16(acc[0], af, __float_as_uint(B0[cur].x), __float_as_uint(B0[cur].y));
            mma_f16(acc[1], af, __float_as_uint(B0[cur].z), __float_as_uint(B0[cur].w));
            mma_f16(acc[2], af, __float_as_uint(B1[cur].x), __float_as_uint(B1[cur].y));
            mma_f16(acc[3], af, __float_as_uint(B1[cur].z), __float_as_uint(B1[cur].w));
            mma_f16(acc[4], af, __float_as_uint(B2[cur].x), __float_as_uint(B2[cur].y));
            mma_f16(acc[5], af, __float_as_uint(B2[cur].z), __float_as_uint(B2[cur].w));

            // Permuted layout: lane owns cols ntp*16 + tq*4..+3, rows g,g+8.
            float* op = out + (size_t)t * 768 + g * 48 + tq * 4;
#pragma unroll
            for (int ntp = 0; ntp < 3; ++ntp) {
                int e = ntp * 2, o = e + 1;
                stwt128(op + ntp * 16,
                        acc[e][0], acc[e][1], acc[o][0], acc[o][1]);   // row g
                stwt128(op + ntp * 16 + 384,
                        acc[e][2], acc[e][3], acc[o][2], acc[o][3]);   // row g+8
            }
        }
    }

    // ================= EXIT: last block resets counters =================
    __syncthreads();
    if (tid == 0) {
        int v = atomicAdd(&g_exit, 1);
        if (v == (int)gridDim.x - 1) {
            atomicExch(&g_done, 0);
            atomicExch(&g_exit, 0);
        }
    }
}

// ---------------------------------------------------------------------------

extern "C" void kernel_launch(void* const* d_in, const int* in_sizes, int n_in,
                              void* d_out, int out_size) {
    // Identify inputs by element count (robust to ordering):
    // x: B (=32768), core0: 512, core1: 10240, core2: 30720, core3: 2560
    const int*   x  = nullptr;  int B = 0;
    const float* c0 = nullptr;
    const float* c1 = nullptr;
    const float* c2 = nullptr;
    const float* c3 = nullptr;
    for (int i = 0; i < n_in; ++i) {
        switch (in_sizes[i]) {
            case 512:   c0 = (const float*)d_in[i]; break;
            case 10240: c1 = (const float*)d_in[i]; break;
            case 30720: c2 = (const float*)d_in[i]; break;
            case 2560:  c3 = (const float*)d_in[i]; break;
            default:    x  = (const int*)d_in[i]; B = in_sizes[i]; break;
        }
    }

    int tokPerBlock = WARPS * T_PER_WARP;            // 32
    int blocks = (B + tokPerBlock - 1) / tokPerBlock;
    if (blocks < 480) blocks = 480;   // barrier progress needs wave-1 cover
    te_fused<<<blocks, 256>>>(x, c0, c1, c2, c3, (float*)d_out, B);
}